// round 8
// baseline (speedup 1.0000x reference)
#include <cuda_runtime.h>
#include <cuda_bf16.h>
#include <cstdint>
#include <math.h>

#define H1 56
#define W1 56
#define BB 16
#define NN 32
#define CC 512
#define RH 60
#define RW 60
#define OH 224
#define OW 224
#define KS 33
#define KC 64

// ---------------- scratch (device globals; no allocation allowed) ----------
__device__ __nv_bfloat16 g_Eb[H1 * W1 * BB * CC];     // 51.4 MB
__device__ __nv_bfloat16 g_Mb[RH * RW * NN * CC];     // 118 MB
__device__ float g_xn[H1 * W1 * BB];
__device__ float g_yn[RH * RW * NN];
__device__ float g_best[H1 * W1 * BB];                // min dsq, via atomicMin(int)
__device__ float g_pix56[BB * H1 * W1];
__device__ float g_pix224[BB * OH * OW];
__device__ float g_tmp224[BB * OH * OW];
__device__ float g_gw[KS];

// ---------------- init ------------------------------------------------------
__global__ void k_init() {
    int i = blockIdx.x * blockDim.x + threadIdx.x;
    if (i < H1 * W1 * BB) g_best[i] = __int_as_float(0x7f800000);
    if (i < KS) {
        float s = 0.f;
        for (int t = 0; t < KS; t++) {
            float x = (t - (KS - 1) / 2) * 0.25f;
            s += expf(-0.5f * x * x);
        }
        float x = (i - (KS - 1) / 2) * 0.25f;
        g_gw[i] = expf(-0.5f * x * x) / s;
    }
}

// ---------------- fp32 -> bf16 conversion + row norms ----------------------
__device__ __forceinline__ void convert_row(const float* __restrict__ src,
                                            __nv_bfloat16* dst, float* norm,
                                            int row, int lane) {
    const float4* s = (const float4*)(src + (size_t)row * CC);
    uint2* d = (uint2*)(dst + (size_t)row * CC);
    float acc = 0.f;
#pragma unroll
    for (int it = 0; it < 4; it++) {
        float4 v = s[it * 32 + lane];
        acc += v.x * v.x + v.y * v.y + v.z * v.z + v.w * v.w;
        __nv_bfloat162 lo = __floats2bfloat162_rn(v.x, v.y);
        __nv_bfloat162 hi = __floats2bfloat162_rn(v.z, v.w);
        uint2 o;
        o.x = *(uint32_t*)&lo;
        o.y = *(uint32_t*)&hi;
        d[it * 32 + lane] = o;
    }
#pragma unroll
    for (int off = 16; off; off >>= 1) acc += __shfl_xor_sync(~0u, acc, off);
    if (lane == 0) norm[row] = acc;
}

__global__ void k_convert_e(const float* __restrict__ src) {
    int gw = (blockIdx.x * blockDim.x + threadIdx.x) >> 5;
    int lane = threadIdx.x & 31;
    if (gw < H1 * W1 * BB) convert_row(src, g_Eb, g_xn, gw, lane);
}
__global__ void k_convert_m(const float* __restrict__ src) {
    int gw = (blockIdx.x * blockDim.x + threadIdx.x) >> 5;
    int lane = threadIdx.x & 31;
    if (gw < RH * RW * NN) convert_row(src, g_Mb, g_yn, gw, lane);
}

// ---------------- main distance kernel --------------------------------------
__device__ __forceinline__ void mma16816(float* d, uint32_t a0, uint32_t a1,
                                         uint32_t a2, uint32_t a3,
                                         uint32_t b0, uint32_t b1) {
    asm volatile(
        "mma.sync.aligned.m16n8k16.row.col.f32.bf16.bf16.f32 "
        "{%0,%1,%2,%3}, {%4,%5,%6,%7}, {%8,%9}, {%0,%1,%2,%3};\n"
        : "+f"(d[0]), "+f"(d[1]), "+f"(d[2]), "+f"(d[3])
        : "r"(a0), "r"(a1), "r"(a2), "r"(a3), "r"(b0), "r"(b1));
}

__device__ __forceinline__ void ldsm_x4(uint32_t& r0, uint32_t& r1,
                                        uint32_t& r2, uint32_t& r3, uint32_t addr) {
    asm volatile("ldmatrix.sync.aligned.m8n8.x4.shared.b16 {%0,%1,%2,%3}, [%4];"
                 : "=r"(r0), "=r"(r1), "=r"(r2), "=r"(r3) : "r"(addr));
}

__device__ __forceinline__ void cp_async16(uint32_t dst, const void* src) {
    asm volatile("cp.async.cg.shared.global [%0], [%1], 16;" ::"r"(dst), "l"(src));
}

__device__ __forceinline__ uint32_t sw128(uint32_t off) {
    return off ^ ((off >> 3) & 0x70);
}

// smem layout (bytes), 128B rows + SW128 swizzle (no padding):
//   A: 2 stages x 400 rows x 128B = 102400
//   B: 2 stages x  32 rows x 128B =   8192
#define A_STAGE_B 51200
#define B_STAGE_B 4096
#define SM_A   0
#define SM_B   102400
#define SM_XN  110592
#define SM_YN  112192
#define SM_Q   112320
#define SM_TOT 112512

#define NWARP 16
#define NTHR  512

__global__ void __launch_bounds__(NTHR, 2) k_dist() {
    extern __shared__ char smem[];
    float* xn_s = (float*)(smem + SM_XN);
    float* yn_s = (float*)(smem + SM_YN);
    int* qoff_s = (int*)(smem + SM_Q);
    const uint32_t sm_u32 = (uint32_t)__cvta_generic_to_shared(smem);
    const uint32_t smA_u32 = sm_u32 + SM_A;
    const uint32_t smB_u32 = sm_u32 + SM_B;

    const int tile = blockIdx.x;
    const int r = tile / RW, s = tile % RW;
    const int tid = threadIdx.x;
    const int wid = tid >> 5, lane = tid & 31;

    if (tid < 25) {
        int h = r - 4 + tid / 5, w = s - 4 + tid % 5;
        qoff_s[tid] = (h >= 0 && h < H1 && w >= 0 && w < W1) ? (h * W1 + w) * BB : -1;
    }
    __syncthreads();
    for (int t = tid; t < 400; t += NTHR) {
        int q = qoff_s[t >> 4];
        xn_s[t] = (q >= 0) ? g_xn[q + (t & 15)] : 0.f;
    }
    if (tid < 32) yn_s[tid] = g_yn[tile * NN + tid];
    __syncthreads();

    // warp's valid slots (warp-uniform): up to 2 (16 warps cover 25 slots)
    int sp[2];
    int nsl = 0;
#pragma unroll
    for (int p = wid; p < 25; p += NWARP)
        if (qoff_s[p] >= 0) sp[nsl++] = p;

    float acc[2][4][4];
#pragma unroll
    for (int a = 0; a < 2; a++)
#pragma unroll
        for (int b = 0; b < 4; b++)
#pragma unroll
            for (int c = 0; c < 4; c++) acc[a][b][c] = 0.f;

    // ---- hoisted A/B load addressing (R8) ----------------------------------
    // A segments: idx = tid + i*512, i<7 ; idx = row*8+seg, row = slot*16+rowin
    //   seg   = tid&7        (invariant over i)
    //   rowin = (tid>>3)&15  (invariant over i : 512/8 = 64 rows, 64%16==0)
    //   slot  = (tid>>7) + 4*i
    const int seg = tid & 7;
    const int rowin = (tid >> 3) & 15;
    const int slot0 = tid >> 7;                       // 0..3
    const uint32_t aswb = sw128(rowin * 128 + seg * 16);
    const uint32_t adst0 = slot0 * 2048 + aswb;       // + i*8192 + buf*A_STAGE_B

    int aoffq[7];                                     // uint4-index into EbV ; -1 invalid
#pragma unroll
    for (int i = 0; i < 7; i++) {
        int slot = slot0 + i * 4;
        int v = -1;
        if (slot < 25) {
            int q = qoff_s[slot];
            if (q >= 0) v = (q + rowin) * (CC / 8) + seg;
        }
        aoffq[i] = v;
    }
    const uint4* EbV = (const uint4*)g_Eb;
    const uint4* MbV = (const uint4*)g_Mb + (size_t)tile * (NN * CC / 8);
    // B: tid<256 -> row = tid>>3
    const uint32_t bdst0 = sw128((tid >> 3) * 128 + seg * 16);
    const uint4* bsrc0 = MbV + (tid >> 3) * 64 + seg;

    auto load_stage = [&](int kc, int buf) {
        const uint32_t abase = smA_u32 + buf * A_STAGE_B + adst0;
        const int kadd = kc * 8;
#pragma unroll
        for (int i = 0; i < 7; i++) {
            if (aoffq[i] >= 0)
                cp_async16(abase + i * 8192, EbV + aoffq[i] + kadd);
        }
        if (tid < 256)
            cp_async16(smB_u32 + buf * B_STAGE_B + bdst0, bsrc0 + kadd);
        asm volatile("cp.async.commit_group;");
    };

    // ldmatrix lane geometry (swizzled 128B rows)
    const uint32_t arow = lane & 15;
    const uint32_t arow128 = arow * 128;
    const uint32_t axor = (arow & 7) << 4;
    const uint32_t akse = (lane >> 4) * 16;           // 0 or 16
    const uint32_t brow = (lane & 7) + ((lane & 16) ? 8 : 0);
    const uint32_t brow128 = brow * 128;
    const uint32_t bxor = (brow & 7) << 4;
    const uint32_t bkse = (lane & 8) ? 16 : 0;

    // prologue: prefetch stages 0 and 1
    load_stage(0, 0);
    load_stage(1, 1);

    for (int kc = 0; kc < CC / KC; kc++) {
        if (kc < CC / KC - 1)
            asm volatile("cp.async.wait_group 1;");
        else
            asm volatile("cp.async.wait_group 0;");
        __syncthreads();

        const int buf = kc & 1;
        const uint32_t abase = smA_u32 + buf * A_STAGE_B;
        const uint32_t bbase = smB_u32 + buf * B_STAGE_B;

#pragma unroll
        for (int ks = 0; ks < 4; ks++) {
            const uint32_t kbyte = ks * 32;
            uint32_t b[2][4];
            const uint32_t baddr = bbase + brow128 + ((bkse + kbyte) ^ bxor);
            ldsm_x4(b[0][0], b[0][1], b[0][2], b[0][3], baddr);
            ldsm_x4(b[1][0], b[1][1], b[1][2], b[1][3], baddr + 16 * 128);
#pragma unroll
            for (int si = 0; si < 2; si++) {
                if (si < nsl) {
                    uint32_t a0, a1, a2, a3;
                    ldsm_x4(a0, a1, a2, a3,
                            abase + sp[si] * 2048 + arow128 + ((akse + kbyte) ^ axor));
                    mma16816(acc[si][0], a0, a1, a2, a3, b[0][0], b[0][1]);
                    mma16816(acc[si][1], a0, a1, a2, a3, b[0][2], b[0][3]);
                    mma16816(acc[si][2], a0, a1, a2, a3, b[1][0], b[1][1]);
                    mma16816(acc[si][3], a0, a1, a2, a3, b[1][2], b[1][3]);
                }
            }
        }
        __syncthreads();   // all warps done reading buf before refill
        if (kc + 2 < CC / KC) load_stage(kc + 2, buf);
    }

    // epilogue: dsq = xn - 2*cross + yn ; min over n ; atomicMin into best
#pragma unroll
    for (int si = 0; si < 2; si++) {
        if (si < nsl) {
            int p = sp[si];
            float xlo = xn_s[p * 16 + (lane >> 2)];
            float xhi = xn_s[p * 16 + 8 + (lane >> 2)];
            float mlo = 3.4e38f, mhi = 3.4e38f;
#pragma unroll
            for (int nb = 0; nb < 4; nb++) {
                int c0 = nb * 8 + ((lane & 3) << 1);
                float y0 = yn_s[c0], y1 = yn_s[c0 + 1];
                mlo = fminf(mlo, fminf(fmaf(-2.f, acc[si][nb][0], xlo) + y0,
                                       fmaf(-2.f, acc[si][nb][1], xlo) + y1));
                mhi = fminf(mhi, fminf(fmaf(-2.f, acc[si][nb][2], xhi) + y0,
                                       fmaf(-2.f, acc[si][nb][3], xhi) + y1));
            }
            mlo = fminf(mlo, __shfl_xor_sync(~0u, mlo, 1));
            mlo = fminf(mlo, __shfl_xor_sync(~0u, mlo, 2));
            mhi = fminf(mhi, __shfl_xor_sync(~0u, mhi, 1));
            mhi = fminf(mhi, __shfl_xor_sync(~0u, mhi, 2));
            if ((lane & 3) == 0) {
                int q = qoff_s[p];
                atomicMin((int*)&g_best[q + (lane >> 2)], __float_as_int(fmaxf(mlo, 0.f)));
                atomicMin((int*)&g_best[q + 8 + (lane >> 2)], __float_as_int(fmaxf(mhi, 0.f)));
            }
        }
    }
}

// ---------------- sqrt + per-b max (img) + pix56 ---------------------------
__global__ void k_finish(float* __restrict__ out) {
    __shared__ float red[256];
    int b = blockIdx.x, tid = threadIdx.x;
    float mx = 0.f;
    for (int i = tid; i < H1 * W1; i += 256) {
        float v = sqrtf(g_best[i * BB + b]);
        g_pix56[b * H1 * W1 + i] = v;
        mx = fmaxf(mx, v);
    }
    red[tid] = mx;
    __syncthreads();
    for (int o = 128; o; o >>= 1) {
        if (tid < o) red[tid] = fmaxf(red[tid], red[tid + o]);
        __syncthreads();
    }
    if (tid == 0) out[b] = red[0];
}

// ---------------- bilinear 56 -> 224 ----------------------------------------
__global__ void k_resize() {
    int idx = blockIdx.x * blockDim.x + threadIdx.x;
    if (idx >= BB * OH * OW) return;
    int b = idx / (OH * OW);
    int rm = idx % (OH * OW);
    int oy = rm / OW, ox = rm % OW;

    float uy = fminf(fmaxf((oy + 0.5f) * 0.25f - 0.5f, 0.f), 55.f);
    float ux = fminf(fmaxf((ox + 0.5f) * 0.25f - 0.5f, 0.f), 55.f);
    int y0 = (int)uy, x0 = (int)ux;
    float fy = uy - y0, fx = ux - x0;
    int y1 = min(y0 + 1, H1 - 1), x1 = min(x0 + 1, W1 - 1);

    const float* p = g_pix56 + b * H1 * W1;
    float v00 = p[y0 * W1 + x0], v01 = p[y0 * W1 + x1];
    float v10 = p[y1 * W1 + x0], v11 = p[y1 * W1 + x1];
    float v = (1.f - fy) * ((1.f - fx) * v00 + fx * v01) +
              fy * ((1.f - fx) * v10 + fx * v11);
    g_pix224[idx] = v;
}

// ---------------- separable gaussian blur, reflect padding ------------------
__device__ __forceinline__ int refl(int i) {
    return i < 0 ? -i : (i > 223 ? 446 - i : i);
}

__global__ void k_vblur() {
    int idx = blockIdx.x * blockDim.x + threadIdx.x;
    if (idx >= BB * OH * OW) return;
    int b = idx / (OH * OW);
    int rm = idx % (OH * OW);
    int y = rm / OW, x = rm % OW;
    const float* p = g_pix224 + b * OH * OW;
    float sum = 0.f;
#pragma unroll
    for (int t = 0; t < KS; t++) {
        int yy = refl(y + t - 16);
        sum += g_gw[t] * p[yy * OW + x];
    }
    g_tmp224[idx] = sum;
}

__global__ void k_hblur(float* __restrict__ out) {
    int idx = blockIdx.x * blockDim.x + threadIdx.x;
    if (idx >= BB * OH * OW) return;
    int b = idx / (OH * OW);
    int rm = idx % (OH * OW);
    int y = rm / OW, x = rm % OW;
    const float* p = g_tmp224 + b * OH * OW;
    float sum = 0.f;
#pragma unroll
    for (int t = 0; t < KS; t++) {
        int xx = refl(x + t - 16);
        sum += g_gw[t] * p[y * OW + xx];
    }
    out[idx] = sum;
}

// ---------------- launch ------------------------------------------------------
extern "C" void kernel_launch(void* const* d_in, const int* in_sizes, int n_in,
                              void* d_out, int out_size) {
    const float* emb = (const float*)d_in[0];
    const float* mem = (const float*)d_in[1];
    float* out = (float*)d_out;

    cudaFuncSetAttribute(k_dist, cudaFuncAttributeMaxDynamicSharedMemorySize, SM_TOT);

    k_init<<<(H1 * W1 * BB + 255) / 256, 256>>>();
    k_convert_e<<<(H1 * W1 * BB + 7) / 8, 256>>>(emb);
    k_convert_m<<<(RH * RW * NN + 7) / 8, 256>>>(mem);
    k_dist<<<RH * RW, NTHR, SM_TOT>>>();
    k_finish<<<BB, 256>>>(out);                       // img -> out[0..15]
    int nt = BB * OH * OW;
    k_resize<<<(nt + 255) / 256, 256>>>();
    k_vblur<<<(nt + 255) / 256, 256>>>();
    k_hblur<<<(nt + 255) / 256, 256>>>(out + BB);     // blur -> out[16..]
}

// round 9
// speedup vs baseline: 1.0407x; 1.0407x over previous
#include <cuda_runtime.h>
#include <cuda_bf16.h>
#include <cstdint>
#include <math.h>

#define H1 56
#define W1 56
#define BB 16
#define NN 32
#define CC 512
#define RH 60
#define RW 60
#define OH 224
#define OW 224
#define KS 33
#define KC 64

// ---------------- scratch (device globals; no allocation allowed) ----------
__device__ __nv_bfloat16 g_Eb[H1 * W1 * BB * CC];     // 51.4 MB
__device__ float g_xn[H1 * W1 * BB];
__device__ float g_best[H1 * W1 * BB];                // min dsq, via atomicMin(int)
__device__ float g_pix56[BB * H1 * W1];
__device__ float g_pix224[BB * OH * OW];
__device__ float g_tmp224[BB * OH * OW];
__device__ float g_gw[KS];

// ---------------- init ------------------------------------------------------
__global__ void k_init() {
    int i = blockIdx.x * blockDim.x + threadIdx.x;
    if (i < H1 * W1 * BB) g_best[i] = __int_as_float(0x7f800000);
    if (i < KS) {
        float s = 0.f;
        for (int t = 0; t < KS; t++) {
            float x = (t - (KS - 1) / 2) * 0.25f;
            s += expf(-0.5f * x * x);
        }
        float x = (i - (KS - 1) / 2) * 0.25f;
        g_gw[i] = expf(-0.5f * x * x) / s;
    }
}

// ---------------- fp32 -> bf16 conversion + row norms (E only) -------------
__global__ void k_convert_e(const float* __restrict__ src) {
    int gw = (blockIdx.x * blockDim.x + threadIdx.x) >> 5;
    int lane = threadIdx.x & 31;
    if (gw >= H1 * W1 * BB) return;
    const float4* s = (const float4*)(src + (size_t)gw * CC);
    uint2* d = (uint2*)(g_Eb + (size_t)gw * CC);
    float acc = 0.f;
#pragma unroll
    for (int it = 0; it < 4; it++) {
        float4 v = s[it * 32 + lane];
        acc += v.x * v.x + v.y * v.y + v.z * v.z + v.w * v.w;
        __nv_bfloat162 lo = __floats2bfloat162_rn(v.x, v.y);
        __nv_bfloat162 hi = __floats2bfloat162_rn(v.z, v.w);
        uint2 o;
        o.x = *(uint32_t*)&lo;
        o.y = *(uint32_t*)&hi;
        d[it * 32 + lane] = o;
    }
#pragma unroll
    for (int off = 16; off; off >>= 1) acc += __shfl_xor_sync(~0u, acc, off);
    if (lane == 0) g_xn[gw] = acc;
}

// ---------------- main distance kernel --------------------------------------
__device__ __forceinline__ void mma16816(float* d, uint32_t a0, uint32_t a1,
                                         uint32_t a2, uint32_t a3,
                                         uint32_t b0, uint32_t b1) {
    asm volatile(
        "mma.sync.aligned.m16n8k16.row.col.f32.bf16.bf16.f32 "
        "{%0,%1,%2,%3}, {%4,%5,%6,%7}, {%8,%9}, {%0,%1,%2,%3};\n"
        : "+f"(d[0]), "+f"(d[1]), "+f"(d[2]), "+f"(d[3])
        : "r"(a0), "r"(a1), "r"(a2), "r"(a3), "r"(b0), "r"(b1));
}

__device__ __forceinline__ void ldsm_x4(uint32_t& r0, uint32_t& r1,
                                        uint32_t& r2, uint32_t& r3, uint32_t addr) {
    asm volatile("ldmatrix.sync.aligned.m8n8.x4.shared.b16 {%0,%1,%2,%3}, [%4];"
                 : "=r"(r0), "=r"(r1), "=r"(r2), "=r"(r3) : "r"(addr));
}

__device__ __forceinline__ void cp_async16(uint32_t dst, const void* src) {
    asm volatile("cp.async.cg.shared.global [%0], [%1], 16;" ::"r"(dst), "l"(src));
}

__device__ __forceinline__ uint32_t sw128(uint32_t off) {
    return off ^ ((off >> 3) & 0x70);
}

// smem layout (bytes), 128B rows + SW128 swizzle (no padding):
//   A: 2 stages x 400 rows x 128B = 102400
//   B: 2 stages x  32 rows x 128B =   8192
#define A_STAGE_B 51200
#define B_STAGE_B 4096
#define SM_A   0
#define SM_B   102400
#define SM_XN  110592
#define SM_YN  112192
#define SM_Q   112320
#define SM_TOT 112512

#define NWARP 16
#define NTHR  512

__global__ void __launch_bounds__(NTHR, 2) k_dist(const float* __restrict__ mem) {
    extern __shared__ char smem[];
    float* xn_s = (float*)(smem + SM_XN);
    float* yn_s = (float*)(smem + SM_YN);
    int* qoff_s = (int*)(smem + SM_Q);
    const uint32_t sm_u32 = (uint32_t)__cvta_generic_to_shared(smem);
    const uint32_t smA_u32 = sm_u32 + SM_A;
    const uint32_t smB_u32 = sm_u32 + SM_B;

    const int tile = blockIdx.x;
    const int r = tile / RW, s = tile % RW;
    const int tid = threadIdx.x;
    const int wid = tid >> 5, lane = tid & 31;

    if (tid < 25) {
        int h = r - 4 + tid / 5, w = s - 4 + tid % 5;
        qoff_s[tid] = (h >= 0 && h < H1 && w >= 0 && w < W1) ? (h * W1 + w) * BB : -1;
    }
    __syncthreads();
    for (int t = tid; t < 400; t += NTHR) {
        int q = qoff_s[t >> 4];
        xn_s[t] = (q >= 0) ? g_xn[q + (t & 15)] : 0.f;
    }

    // warp's valid slots (warp-uniform): up to 2 (16 warps cover 25 slots)
    int sp[2];
    int nsl = 0;
#pragma unroll
    for (int p = wid; p < 25; p += NWARP)
        if (qoff_s[p] >= 0) sp[nsl++] = p;

    float acc[2][4][4];
#pragma unroll
    for (int a = 0; a < 2; a++)
#pragma unroll
        for (int b = 0; b < 4; b++)
#pragma unroll
            for (int c = 0; c < 4; c++) acc[a][b][c] = 0.f;

    // ---- hoisted A load addressing -----------------------------------------
    const int seg = tid & 7;
    const int rowin = (tid >> 3) & 15;
    const int slot0 = tid >> 7;                       // 0..3
    const uint32_t adst0 = slot0 * 2048 + sw128(rowin * 128 + seg * 16);

    int aoffq[7];                                     // uint4-index into EbV ; -1 invalid
#pragma unroll
    for (int i = 0; i < 7; i++) {
        int slot = slot0 + i * 4;
        int v = -1;
        if (slot < 25) {
            int q = qoff_s[slot];
            if (q >= 0) v = (q + rowin) * (CC / 8) + seg;
        }
        aoffq[i] = v;
    }
    const uint4* EbV = (const uint4*)g_Eb;

    auto load_stage = [&](int kc, int buf) {        // A only (cp.async)
        const uint32_t abase = smA_u32 + buf * A_STAGE_B + adst0;
        const int kadd = kc * 8;
#pragma unroll
        for (int i = 0; i < 7; i++) {
            if (aoffq[i] >= 0)
                cp_async16(abase + i * 8192, EbV + aoffq[i] + kadd);
        }
        asm volatile("cp.async.commit_group;");
    };

    // ---- B path: fp32 M read + in-register bf16 convert + STS (fused) ------
    const int brow = tid >> 4;                        // 0..31
    const int bf4 = tid & 15;                         // 0..15 (float4 within row-chunk)
    const float4* bsrcf = (const float4*)(mem + ((size_t)tile * NN + brow) * CC) + bf4;
    const uint32_t bdst = smB_u32 + sw128(brow * 128 + bf4 * 8);
    float ynacc = 0.f;

    auto b_convert_store = [&](float4 v, int buf) {
        ynacc += v.x * v.x + v.y * v.y + v.z * v.z + v.w * v.w;
        __nv_bfloat162 lo = __floats2bfloat162_rn(v.x, v.y);
        __nv_bfloat162 hi = __floats2bfloat162_rn(v.z, v.w);
        uint32_t plo = *(uint32_t*)&lo, phi = *(uint32_t*)&hi;
        asm volatile("st.shared.v2.b32 [%0], {%1,%2};"
                     :: "r"(bdst + buf * B_STAGE_B), "r"(plo), "r"(phi));
    };

    // ldmatrix lane geometry (swizzled 128B rows)
    const uint32_t arow = lane & 15;
    const uint32_t arow128 = arow * 128;
    const uint32_t axor = (arow & 7) << 4;
    const uint32_t akse = (lane >> 4) * 16;           // 0 or 16
    const uint32_t brow_l = (lane & 7) + ((lane & 16) ? 8 : 0);
    const uint32_t brow128 = brow_l * 128;
    const uint32_t bxor = (brow_l & 7) << 4;
    const uint32_t bkse = (lane & 8) ? 16 : 0;

    // prologue: B0 convert+store ; prefetch A0, A1 ; B1 fp32 into regs
    b_convert_store(bsrcf[0], 0);
    load_stage(0, 0);
    load_stage(1, 1);
    float4 fcur = bsrcf[16];                          // stage 1 (kc*16 float4 stride)

    for (int kc = 0; kc < CC / KC; kc++) {
        if (kc < CC / KC - 1)
            asm volatile("cp.async.wait_group 1;");
        else
            asm volatile("cp.async.wait_group 0;");
        __syncthreads();

        const int buf = kc & 1;
        const uint32_t abase = smA_u32 + buf * A_STAGE_B;
        const uint32_t bbase = smB_u32 + buf * B_STAGE_B;

#pragma unroll
        for (int ks = 0; ks < 4; ks++) {
            const uint32_t kbyte = ks * 32;
            uint32_t b[2][4];
            const uint32_t baddr = bbase + brow128 + ((bkse + kbyte) ^ bxor);
            ldsm_x4(b[0][0], b[0][1], b[0][2], b[0][3], baddr);
            ldsm_x4(b[1][0], b[1][1], b[1][2], b[1][3], baddr + 16 * 128);
#pragma unroll
            for (int si = 0; si < 2; si++) {
                if (si < nsl) {
                    uint32_t a0, a1, a2, a3;
                    ldsm_x4(a0, a1, a2, a3,
                            abase + sp[si] * 2048 + arow128 + ((akse + kbyte) ^ axor));
                    mma16816(acc[si][0], a0, a1, a2, a3, b[0][0], b[0][1]);
                    mma16816(acc[si][1], a0, a1, a2, a3, b[0][2], b[0][3]);
                    mma16816(acc[si][2], a0, a1, a2, a3, b[1][0], b[1][1]);
                    mma16816(acc[si][3], a0, a1, a2, a3, b[1][2], b[1][3]);
                }
            }
        }
        __syncthreads();   // all warps done reading buf before refill
        if (kc + 1 < CC / KC) b_convert_store(fcur, (kc + 1) & 1);
        if (kc + 2 < CC / KC) {
            fcur = bsrcf[(kc + 2) * 16];
            load_stage(kc + 2, buf);
        }
    }

    // ---- yn: reduce per-row sums of squares (16 threads per row) -----------
    float ya = ynacc;
#pragma unroll
    for (int off = 8; off; off >>= 1) ya += __shfl_xor_sync(~0u, ya, off);
    if ((lane & 15) == 0) yn_s[brow] = ya;
    __syncthreads();

    // epilogue: dsq = xn - 2*cross + yn ; min over n ; atomicMin into best
#pragma unroll
    for (int si = 0; si < 2; si++) {
        if (si < nsl) {
            int p = sp[si];
            float xlo = xn_s[p * 16 + (lane >> 2)];
            float xhi = xn_s[p * 16 + 8 + (lane >> 2)];
            float mlo = 3.4e38f, mhi = 3.4e38f;
#pragma unroll
            for (int nb = 0; nb < 4; nb++) {
                int c0 = nb * 8 + ((lane & 3) << 1);
                float y0 = yn_s[c0], y1 = yn_s[c0 + 1];
                mlo = fminf(mlo, fminf(fmaf(-2.f, acc[si][nb][0], xlo) + y0,
                                       fmaf(-2.f, acc[si][nb][1], xlo) + y1));
                mhi = fminf(mhi, fminf(fmaf(-2.f, acc[si][nb][2], xhi) + y0,
                                       fmaf(-2.f, acc[si][nb][3], xhi) + y1));
            }
            mlo = fminf(mlo, __shfl_xor_sync(~0u, mlo, 1));
            mlo = fminf(mlo, __shfl_xor_sync(~0u, mlo, 2));
            mhi = fminf(mhi, __shfl_xor_sync(~0u, mhi, 1));
            mhi = fminf(mhi, __shfl_xor_sync(~0u, mhi, 2));
            if ((lane & 3) == 0) {
                int q = qoff_s[p];
                atomicMin((int*)&g_best[q + (lane >> 2)], __float_as_int(fmaxf(mlo, 0.f)));
                atomicMin((int*)&g_best[q + 8 + (lane >> 2)], __float_as_int(fmaxf(mhi, 0.f)));
            }
        }
    }
}

// ---------------- sqrt + per-b max (img) + pix56 ---------------------------
__global__ void k_finish(float* __restrict__ out) {
    __shared__ float red[256];
    int b = blockIdx.x, tid = threadIdx.x;
    float mx = 0.f;
    for (int i = tid; i < H1 * W1; i += 256) {
        float v = sqrtf(g_best[i * BB + b]);
        g_pix56[b * H1 * W1 + i] = v;
        mx = fmaxf(mx, v);
    }
    red[tid] = mx;
    __syncthreads();
    for (int o = 128; o; o >>= 1) {
        if (tid < o) red[tid] = fmaxf(red[tid], red[tid + o]);
        __syncthreads();
    }
    if (tid == 0) out[b] = red[0];
}

// ---------------- bilinear 56 -> 224 ----------------------------------------
__global__ void k_resize() {
    int idx = blockIdx.x * blockDim.x + threadIdx.x;
    if (idx >= BB * OH * OW) return;
    int b = idx / (OH * OW);
    int rm = idx % (OH * OW);
    int oy = rm / OW, ox = rm % OW;

    float uy = fminf(fmaxf((oy + 0.5f) * 0.25f - 0.5f, 0.f), 55.f);
    float ux = fminf(fmaxf((ox + 0.5f) * 0.25f - 0.5f, 0.f), 55.f);
    int y0 = (int)uy, x0 = (int)ux;
    float fy = uy - y0, fx = ux - x0;
    int y1 = min(y0 + 1, H1 - 1), x1 = min(x0 + 1, W1 - 1);

    const float* p = g_pix56 + b * H1 * W1;
    float v00 = p[y0 * W1 + x0], v01 = p[y0 * W1 + x1];
    float v10 = p[y1 * W1 + x0], v11 = p[y1 * W1 + x1];
    float v = (1.f - fy) * ((1.f - fx) * v00 + fx * v01) +
              fy * ((1.f - fx) * v10 + fx * v11);
    g_pix224[idx] = v;
}

// ---------------- separable gaussian blur, reflect padding ------------------
__device__ __forceinline__ int refl(int i) {
    return i < 0 ? -i : (i > 223 ? 446 - i : i);
}

__global__ void k_vblur() {
    int idx = blockIdx.x * blockDim.x + threadIdx.x;
    if (idx >= BB * OH * OW) return;
    int b = idx / (OH * OW);
    int rm = idx % (OH * OW);
    int y = rm / OW, x = rm % OW;
    const float* p = g_pix224 + b * OH * OW;
    float sum = 0.f;
#pragma unroll
    for (int t = 0; t < KS; t++) {
        int yy = refl(y + t - 16);
        sum += g_gw[t] * p[yy * OW + x];
    }
    g_tmp224[idx] = sum;
}

__global__ void k_hblur(float* __restrict__ out) {
    int idx = blockIdx.x * blockDim.x + threadIdx.x;
    if (idx >= BB * OH * OW) return;
    int b = idx / (OH * OW);
    int rm = idx % (OH * OW);
    int y = rm / OW, x = rm % OW;
    const float* p = g_tmp224 + b * OH * OW;
    float sum = 0.f;
#pragma unroll
    for (int t = 0; t < KS; t++) {
        int xx = refl(x + t - 16);
        sum += g_gw[t] * p[y * OW + xx];
    }
    out[idx] = sum;
}

// ---------------- launch ------------------------------------------------------
extern "C" void kernel_launch(void* const* d_in, const int* in_sizes, int n_in,
                              void* d_out, int out_size) {
    const float* emb = (const float*)d_in[0];
    const float* mem = (const float*)d_in[1];
    float* out = (float*)d_out;

    cudaFuncSetAttribute(k_dist, cudaFuncAttributeMaxDynamicSharedMemorySize, SM_TOT);

    k_init<<<(H1 * W1 * BB + 255) / 256, 256>>>();
    k_convert_e<<<(H1 * W1 * BB + 7) / 8, 256>>>(emb);
    k_dist<<<RH * RW, NTHR, SM_TOT>>>(mem);
    k_finish<<<BB, 256>>>(out);                       // img -> out[0..15]
    int nt = BB * OH * OW;
    k_resize<<<(nt + 255) / 256, 256>>>();
    k_vblur<<<(nt + 255) / 256, 256>>>();
    k_hblur<<<(nt + 255) / 256, 256>>>(out + BB);     // blur -> out[16..]
}

// round 10
// speedup vs baseline: 1.0600x; 1.0185x over previous
#include <cuda_runtime.h>
#include <cuda_bf16.h>
#include <cstdint>
#include <math.h>

#define H1 56
#define W1 56
#define BB 16
#define NN 32
#define CC 512
#define RH 60
#define RW 60
#define OH 224
#define OW 224
#define KS 33
#define KC 64

// ---------------- scratch (device globals; no allocation allowed) ----------
__device__ __nv_bfloat16 g_Eb[H1 * W1 * BB * CC];     // 51.4 MB
__device__ float g_xn[H1 * W1 * BB];
__device__ float g_best[H1 * W1 * BB];                // min dsq, via atomicMin(int)
__device__ float g_pix56[BB * H1 * W1];
__device__ float g_tmp[BB * OH * H1];                 // W·P stage (16x224x56)
__device__ float g_W[OH * H1];                        // fused resize+blur matrix
__device__ float g_Wt[H1 * OH];                       // its transpose

// ---------------- init: best=+inf, out-max=0, fused W matrix ---------------
__global__ void k_init(float* __restrict__ out) {
    int i = blockIdx.x * blockDim.x + threadIdx.x;
    if (i < H1 * W1 * BB) g_best[i] = __int_as_float(0x7f800000);
    if (i < BB) out[i] = 0.f;                         // for atomicMax in k_finish
    if (i < OH) {
        // gaussian weights (each thread recomputes; trivial)
        float gw[KS], ssum = 0.f;
#pragma unroll
        for (int t = 0; t < KS; t++) {
            float x = (t - (KS - 1) / 2) * 0.25f;
            gw[t] = expf(-0.5f * x * x);
            ssum += gw[t];
        }
        float acc[H1];
#pragma unroll
        for (int k = 0; k < H1; k++) acc[k] = 0.f;
        for (int t = 0; t < KS; t++) {
            int yy = i + t - 16;
            yy = yy < 0 ? -yy : (yy > 223 ? 446 - yy : yy);   // reflect
            float uy = fminf(fmaxf((yy + 0.5f) * 0.25f - 0.5f, 0.f), 55.f);
            int y0 = (int)uy;
            float fy = uy - y0;
            int y1 = min(y0 + 1, H1 - 1);
            float g = gw[t] / ssum;
            acc[y0] += g * (1.f - fy);
            acc[y1] += g * fy;
        }
        for (int k = 0; k < H1; k++) {
            g_W[i * H1 + k] = acc[k];
            g_Wt[k * OH + i] = acc[k];
        }
    }
}

// ---------------- fp32 -> bf16 conversion + row norms (E only) -------------
__global__ void k_convert_e(const float* __restrict__ src) {
    int gw = (blockIdx.x * blockDim.x + threadIdx.x) >> 5;
    int lane = threadIdx.x & 31;
    if (gw >= H1 * W1 * BB) return;
    const float4* s = (const float4*)(src + (size_t)gw * CC);
    uint2* d = (uint2*)(g_Eb + (size_t)gw * CC);
    float acc = 0.f;
#pragma unroll
    for (int it = 0; it < 4; it++) {
        float4 v = s[it * 32 + lane];
        acc += v.x * v.x + v.y * v.y + v.z * v.z + v.w * v.w;
        __nv_bfloat162 lo = __floats2bfloat162_rn(v.x, v.y);
        __nv_bfloat162 hi = __floats2bfloat162_rn(v.z, v.w);
        uint2 o;
        o.x = *(uint32_t*)&lo;
        o.y = *(uint32_t*)&hi;
        d[it * 32 + lane] = o;
    }
#pragma unroll
    for (int off = 16; off; off >>= 1) acc += __shfl_xor_sync(~0u, acc, off);
    if (lane == 0) g_xn[gw] = acc;
}

// ---------------- main distance kernel --------------------------------------
__device__ __forceinline__ void mma16816(float* d, uint32_t a0, uint32_t a1,
                                         uint32_t a2, uint32_t a3,
                                         uint32_t b0, uint32_t b1) {
    asm volatile(
        "mma.sync.aligned.m16n8k16.row.col.f32.bf16.bf16.f32 "
        "{%0,%1,%2,%3}, {%4,%5,%6,%7}, {%8,%9}, {%0,%1,%2,%3};\n"
        : "+f"(d[0]), "+f"(d[1]), "+f"(d[2]), "+f"(d[3])
        : "r"(a0), "r"(a1), "r"(a2), "r"(a3), "r"(b0), "r"(b1));
}

__device__ __forceinline__ void ldsm_x4(uint32_t& r0, uint32_t& r1,
                                        uint32_t& r2, uint32_t& r3, uint32_t addr) {
    asm volatile("ldmatrix.sync.aligned.m8n8.x4.shared.b16 {%0,%1,%2,%3}, [%4];"
                 : "=r"(r0), "=r"(r1), "=r"(r2), "=r"(r3) : "r"(addr));
}

__device__ __forceinline__ void cp_async16(uint32_t dst, const void* src) {
    asm volatile("cp.async.cg.shared.global [%0], [%1], 16;" ::"r"(dst), "l"(src));
}

__device__ __forceinline__ uint32_t sw128(uint32_t off) {
    return off ^ ((off >> 3) & 0x70);
}

// smem layout (bytes), 128B rows + SW128 swizzle (no padding):
#define A_STAGE_B 51200
#define B_STAGE_B 4096
#define SM_A   0
#define SM_B   102400
#define SM_XN  110592
#define SM_YN  112192
#define SM_Q   112320
#define SM_TOT 112512

#define NWARP 16
#define NTHR  512

__global__ void __launch_bounds__(NTHR, 2) k_dist(const float* __restrict__ mem) {
    extern __shared__ char smem[];
    float* xn_s = (float*)(smem + SM_XN);
    float* yn_s = (float*)(smem + SM_YN);
    int* qoff_s = (int*)(smem + SM_Q);
    const uint32_t sm_u32 = (uint32_t)__cvta_generic_to_shared(smem);
    const uint32_t smA_u32 = sm_u32 + SM_A;
    const uint32_t smB_u32 = sm_u32 + SM_B;

    const int tile = blockIdx.x;
    const int r = tile / RW, s = tile % RW;
    const int tid = threadIdx.x;
    const int wid = tid >> 5, lane = tid & 31;

    if (tid < 25) {
        int h = r - 4 + tid / 5, w = s - 4 + tid % 5;
        qoff_s[tid] = (h >= 0 && h < H1 && w >= 0 && w < W1) ? (h * W1 + w) * BB : -1;
    }
    __syncthreads();
    for (int t = tid; t < 400; t += NTHR) {
        int q = qoff_s[t >> 4];
        xn_s[t] = (q >= 0) ? g_xn[q + (t & 15)] : 0.f;
    }

    // warp's valid slots (warp-uniform): up to 2 (16 warps cover 25 slots)
    int sp[2];
    int nsl = 0;
#pragma unroll
    for (int p = wid; p < 25; p += NWARP)
        if (qoff_s[p] >= 0) sp[nsl++] = p;

    float acc[2][4][4];
#pragma unroll
    for (int a = 0; a < 2; a++)
#pragma unroll
        for (int b = 0; b < 4; b++)
#pragma unroll
            for (int c = 0; c < 4; c++) acc[a][b][c] = 0.f;

    // ---- hoisted A load addressing -----------------------------------------
    const int seg = tid & 7;
    const int rowin = (tid >> 3) & 15;
    const int slot0 = tid >> 7;                       // 0..3
    const uint32_t adst0 = slot0 * 2048 + sw128(rowin * 128 + seg * 16);

    int aoffq[7];
#pragma unroll
    for (int i = 0; i < 7; i++) {
        int slot = slot0 + i * 4;
        int v = -1;
        if (slot < 25) {
            int q = qoff_s[slot];
            if (q >= 0) v = (q + rowin) * (CC / 8) + seg;
        }
        aoffq[i] = v;
    }
    const uint4* EbV = (const uint4*)g_Eb;

    auto load_stage = [&](int kc, int buf) {        // A only (cp.async)
        const uint32_t abase = smA_u32 + buf * A_STAGE_B + adst0;
        const int kadd = kc * 8;
#pragma unroll
        for (int i = 0; i < 7; i++) {
            if (aoffq[i] >= 0)
                cp_async16(abase + i * 8192, EbV + aoffq[i] + kadd);
        }
        asm volatile("cp.async.commit_group;");
    };

    // ---- B path: fp32 M read + in-register bf16 convert + STS (fused) ------
    const int brow = tid >> 4;                        // 0..31
    const int bf4 = tid & 15;                         // 0..15
    const float4* bsrcf = (const float4*)(mem + ((size_t)tile * NN + brow) * CC) + bf4;
    const uint32_t bdst = smB_u32 + sw128(brow * 128 + bf4 * 8);
    float ynacc = 0.f;

    auto b_convert_store = [&](float4 v, int buf) {
        ynacc += v.x * v.x + v.y * v.y + v.z * v.z + v.w * v.w;
        __nv_bfloat162 lo = __floats2bfloat162_rn(v.x, v.y);
        __nv_bfloat162 hi = __floats2bfloat162_rn(v.z, v.w);
        uint32_t plo = *(uint32_t*)&lo, phi = *(uint32_t*)&hi;
        asm volatile("st.shared.v2.b32 [%0], {%1,%2};"
                     :: "r"(bdst + buf * B_STAGE_B), "r"(plo), "r"(phi));
    };

    // ldmatrix lane geometry (swizzled 128B rows)
    const uint32_t arow = lane & 15;
    const uint32_t arow128 = arow * 128;
    const uint32_t axor = (arow & 7) << 4;
    const uint32_t akse = (lane >> 4) * 16;
    const uint32_t brow_l = (lane & 7) + ((lane & 16) ? 8 : 0);
    const uint32_t brow128 = brow_l * 128;
    const uint32_t bxor = (brow_l & 7) << 4;
    const uint32_t bkse = (lane & 8) ? 16 : 0;

    // prologue
    b_convert_store(bsrcf[0], 0);
    load_stage(0, 0);
    load_stage(1, 1);
    float4 fcur = bsrcf[16];

    for (int kc = 0; kc < CC / KC; kc++) {
        if (kc < CC / KC - 1)
            asm volatile("cp.async.wait_group 1;");
        else
            asm volatile("cp.async.wait_group 0;");
        __syncthreads();

        const int buf = kc & 1;
        const uint32_t abase = smA_u32 + buf * A_STAGE_B;
        const uint32_t bbase = smB_u32 + buf * B_STAGE_B;

#pragma unroll
        for (int ks = 0; ks < 4; ks++) {
            const uint32_t kbyte = ks * 32;
            uint32_t b[2][4];
            const uint32_t baddr = bbase + brow128 + ((bkse + kbyte) ^ bxor);
            ldsm_x4(b[0][0], b[0][1], b[0][2], b[0][3], baddr);
            ldsm_x4(b[1][0], b[1][1], b[1][2], b[1][3], baddr + 16 * 128);
#pragma unroll
            for (int si = 0; si < 2; si++) {
                if (si < nsl) {
                    uint32_t a0, a1, a2, a3;
                    ldsm_x4(a0, a1, a2, a3,
                            abase + sp[si] * 2048 + arow128 + ((akse + kbyte) ^ axor));
                    mma16816(acc[si][0], a0, a1, a2, a3, b[0][0], b[0][1]);
                    mma16816(acc[si][1], a0, a1, a2, a3, b[0][2], b[0][3]);
                    mma16816(acc[si][2], a0, a1, a2, a3, b[1][0], b[1][1]);
                    mma16816(acc[si][3], a0, a1, a2, a3, b[1][2], b[1][3]);
                }
            }
        }
        __syncthreads();
        if (kc + 1 < CC / KC) b_convert_store(fcur, (kc + 1) & 1);
        if (kc + 2 < CC / KC) {
            fcur = bsrcf[(kc + 2) * 16];
            load_stage(kc + 2, buf);
        }
    }

    // ---- yn reduce ----------------------------------------------------------
    float ya = ynacc;
#pragma unroll
    for (int off = 8; off; off >>= 1) ya += __shfl_xor_sync(~0u, ya, off);
    if ((lane & 15) == 0) yn_s[brow] = ya;
    __syncthreads();

    // epilogue: dsq = xn - 2*cross + yn ; min over n ; atomicMin into best
#pragma unroll
    for (int si = 0; si < 2; si++) {
        if (si < nsl) {
            int p = sp[si];
            float xlo = xn_s[p * 16 + (lane >> 2)];
            float xhi = xn_s[p * 16 + 8 + (lane >> 2)];
            float mlo = 3.4e38f, mhi = 3.4e38f;
#pragma unroll
            for (int nb = 0; nb < 4; nb++) {
                int c0 = nb * 8 + ((lane & 3) << 1);
                float y0 = yn_s[c0], y1 = yn_s[c0 + 1];
                mlo = fminf(mlo, fminf(fmaf(-2.f, acc[si][nb][0], xlo) + y0,
                                       fmaf(-2.f, acc[si][nb][1], xlo) + y1));
                mhi = fminf(mhi, fminf(fmaf(-2.f, acc[si][nb][2], xhi) + y0,
                                       fmaf(-2.f, acc[si][nb][3], xhi) + y1));
            }
            mlo = fminf(mlo, __shfl_xor_sync(~0u, mlo, 1));
            mlo = fminf(mlo, __shfl_xor_sync(~0u, mlo, 2));
            mhi = fminf(mhi, __shfl_xor_sync(~0u, mhi, 1));
            mhi = fminf(mhi, __shfl_xor_sync(~0u, mhi, 2));
            if ((lane & 3) == 0) {
                int q = qoff_s[p];
                atomicMin((int*)&g_best[q + (lane >> 2)], __float_as_int(fmaxf(mlo, 0.f)));
                atomicMin((int*)&g_best[q + 8 + (lane >> 2)], __float_as_int(fmaxf(mhi, 0.f)));
            }
        }
    }
}

// ---------------- sqrt + per-b max (atomic) + pix56 transpose --------------
// grid = 16 b x 7 slices of 448 ; out[b] pre-zeroed in k_init
__global__ void k_finish(float* __restrict__ out) {
    __shared__ float red[14];
    const int b = blockIdx.x & 15;
    const int i = (blockIdx.x >> 4) * 448 + threadIdx.x;
    float v = sqrtf(g_best[i * BB + b]);
    g_pix56[b * (H1 * W1) + i] = v;
#pragma unroll
    for (int off = 16; off; off >>= 1) v = fmaxf(v, __shfl_xor_sync(~0u, v, off));
    if ((threadIdx.x & 31) == 0) red[threadIdx.x >> 5] = v;
    __syncthreads();
    if (threadIdx.x == 0) {
        float m = red[0];
#pragma unroll
        for (int w = 1; w < 14; w++) m = fmaxf(m, red[w]);
        atomicMax((int*)&out[b], __float_as_int(m));
    }
}

// ---------------- fused resize+blur: out = W * P * W^T ----------------------
// stage 1: tmp[b][oy][x] = sum_k W[oy][k] * pix56[b][k][x]
__global__ void k_vres() {
    int idx = blockIdx.x * blockDim.x + threadIdx.x;
    if (idx >= BB * OH * H1) return;
    int x = idx % H1;
    int oy = (idx / H1) % OH;
    int b = idx / (OH * H1);
    const float* Wr = g_W + oy * H1;
    const float* P = g_pix56 + b * (H1 * W1) + x;
    float sum = 0.f;
#pragma unroll 8
    for (int k = 0; k < H1; k++) sum += Wr[k] * P[k * W1];
    g_tmp[idx] = sum;
}

// stage 2: out[b][oy][ox] = sum_k tmp[b][oy][k] * Wt[k][ox]
__global__ void k_hres(float* __restrict__ out) {
    int idx = blockIdx.x * blockDim.x + threadIdx.x;
    if (idx >= BB * OH * OW) return;
    int ox = idx % OW;
    int row = idx / OW;                                // b*OH + oy
    const float* T = g_tmp + row * H1;
    const float* Wc = g_Wt + ox;
    float sum = 0.f;
#pragma unroll 8
    for (int k = 0; k < H1; k++) sum += T[k] * Wc[k * OH];
    out[idx] = sum;
}

// ---------------- launch ------------------------------------------------------
extern "C" void kernel_launch(void* const* d_in, const int* in_sizes, int n_in,
                              void* d_out, int out_size) {
    const float* emb = (const float*)d_in[0];
    const float* mem = (const float*)d_in[1];
    float* out = (float*)d_out;

    cudaFuncSetAttribute(k_dist, cudaFuncAttributeMaxDynamicSharedMemorySize, SM_TOT);

    k_init<<<(H1 * W1 * BB + 255) / 256, 256>>>(out);
    k_convert_e<<<(H1 * W1 * BB + 7) / 8, 256>>>(emb);
    k_dist<<<RH * RW, NTHR, SM_TOT>>>(mem);
    k_finish<<<BB * 7, 448>>>(out);                   // img -> out[0..15]
    k_vres<<<(BB * OH * H1 + 255) / 256, 256>>>();
    k_hres<<<(BB * OH * OW + 255) / 256, 256>>>(out + BB);  // blur -> out[16..]
}